// round 16
// baseline (speedup 1.0000x reference)
#include <cuda_runtime.h>
#include <cuda_bf16.h>
#include <cstdint>

// ---------------------------------------------------------------------------
// Problem constants
// ---------------------------------------------------------------------------
#define D_MODEL 1024
#define NHEAD   16
#define HDIM    64
#define TXT_LEN 226
#define CHUNKS  4
#define SEQ_TXT 904
#define VID_LEN 3328
#define CHUNK_VID 1024
#define T_ATTN  1250
#define SEG_PAD 1280
#define M_ATTN  5000
#define M_PAD   5120
#define SEQ_SSM 4232
#define ATTN_SCALE 0.125f
#define NCHUNK  34

// ---------------------------------------------------------------------------
// Scratch (static __device__)
// ---------------------------------------------------------------------------
__device__ float g_curp [5242880];
__device__ float g_qt   [5120000];
__device__ float g_kt   [5120000];
__device__ float g_vt   [5120000];
__device__ float g_attnp[5242880];
__device__ float g_proj [5242880];
__device__ float g_emb  [4333568];
__device__ float g_embp [4456448];
__device__ float g_hlocp[4456448];
__device__ float g_hp   [4456448];
__device__ float g_emb2 [4333568];
__device__ float g_revp [4456448];
__device__ float g_carry[34816];
__device__ float g_wqkv[3145728];
__device__ float g_bqkv[3072];
__device__ float g_wo  [1048576];
__device__ float g_win [1048576];
__device__ float g_wout[1048576];
__device__ float g_tg  [4096];

__device__ __forceinline__ float tf32_rna(float x) {
  float r;
  asm("cvt.rna.tf32.f32 %0, %1;" : "=f"(r) : "f"(x));
  return r;
}

__device__ __forceinline__ size_t aperm_off(int r, int c) {
  const int rb = r >> 7, rl = r & 127;
  const int kt = c >> 4, cl = c & 15;
  const int g  = rl >> 4;
  const int j  = ((rl >> 3) & 1) | (((cl >> 2) & 1) << 1);
  const int lane = ((rl & 7) << 2) | (cl & 3);
  return ((size_t)(rb * 64 + kt)) * 2048 + (((g << 1) + (cl >> 3)) << 7) +
         (lane << 2) + j;
}

struct APermIdx { int r0, c0; size_t off; };
__device__ __forceinline__ APermIdx aperm_decode(int idx) {
  const int lane = idx & 31;
  const int half = (idx >> 5) & 1;
  const int g    = (idx >> 6) & 7;
  const int kt   = (idx >> 9) & 63;
  const int rb   = idx >> 15;
  APermIdx o;
  o.r0  = rb * 128 + g * 16 + (lane >> 2);
  o.c0  = kt * 16 + half * 8 + (lane & 3);
  o.off = ((size_t)(rb * 64 + kt)) * 2048 + (((g << 1) + half) << 7) + (lane << 2);
  return o;
}

__device__ __forceinline__ void cp16(uint32_t s, const void* g) {
  asm volatile("cp.async.cg.shared.global [%0], [%1], 16;" :: "r"(s), "l"(g));
}

__device__ __forceinline__ int rev_map(int i) {
  if (i < SEQ_TXT) {
    const int c = i / TXT_LEN;
    return (3 - c) * TXT_LEN + (i - c * TXT_LEN);
  }
  return 5135 - i;
}

__device__ __forceinline__ void rope_apply(float* x, int t) {
  const int p = t - TXT_LEN;
  const float fpos = (float)(p >> 8);
  const int rem = p & 255;
  const float hpos = (float)(rem >> 4);
  const float wpos = (float)(rem & 15);
#pragma unroll
  for (int i = 0; i < 8; i++) {
    const float ang = fpos * __powf(10000.f, -(float)i * 0.125f);
    float sn, cs; sincosf(ang, &sn, &cs);
    const float x1 = x[i], x2 = x[8 + i];
    x[i]     = x1 * cs - x2 * sn;
    x[8 + i] = x1 * sn + x2 * cs;
  }
#pragma unroll
  for (int i = 0; i < 12; i++) {
    const float ang = hpos * __powf(10000.f, -(float)i * (1.f / 12.f));
    float sn, cs; sincosf(ang, &sn, &cs);
    const float x1 = x[16 + i], x2 = x[28 + i];
    x[16 + i] = x1 * cs - x2 * sn;
    x[28 + i] = x1 * sn + x2 * cs;
  }
#pragma unroll
  for (int i = 0; i < 12; i++) {
    const float ang = wpos * __powf(10000.f, -(float)i * (1.f / 12.f));
    float sn, cs; sincosf(ang, &sn, &cs);
    const float x1 = x[40 + i], x2 = x[52 + i];
    x[40 + i] = x1 * cs - x2 * sn;
    x[52 + i] = x1 * sn + x2 * cs;
  }
}

// ---------------------------------------------------------------------------
// Weight packing — coalesced float2 bperm writers.
// float2 index decode: idx = nb*65536 + kt*1024 + n8*64 + kb*32 + lane
//  -> covers (k0, c) and (k0+4, c), k0 = kt*16+kb*8+(lane&3),
//     c = nb*128 + n8*8 + (lane>>2)
// ---------------------------------------------------------------------------
__global__ void pack_qkv_perm2(const float* __restrict__ Wq,
                               const float* __restrict__ Wk,
                               const float* __restrict__ Wv,
                               float* __restrict__ dst) {
  const int idx = blockIdx.x * 256 + threadIdx.x;   // < 1572864
  const int lane = idx & 31;
  const int kb = (idx >> 5) & 1;
  const int n8 = (idx >> 6) & 15;
  const int kt = (idx >> 10) & 63;
  const int nb = idx >> 16;
  const int k0 = kt * 16 + kb * 8 + (lane & 3);
  const int cg = nb * 128 + n8 * 8 + (lane >> 2);
  const float* W = (cg < 1024) ? Wq : (cg < 2048) ? Wk : Wv;
  const int c = cg & 1023;
  float2 o;
  o.x = tf32_rna(W[(size_t)k0 * 1024 + c]);
  o.y = tf32_rna(W[(size_t)(k0 + 4) * 1024 + c]);
  reinterpret_cast<float2*>(dst)[idx] = o;
}

__global__ void pack3_b_perm2(const float* __restrict__ W0,
                              const float* __restrict__ W1,
                              const float* __restrict__ W2,
                              float* __restrict__ D0,
                              float* __restrict__ D1,
                              float* __restrict__ D2) {
  const int gidx = blockIdx.x * 256 + threadIdx.x;  // < 1572864
  const int w  = gidx >> 19;                         // 0..2
  const int idx = gidx & 524287;                     // per-weight float2 idx
  const float* W = (w == 0) ? W0 : (w == 1) ? W1 : W2;
  float* D       = (w == 0) ? D0 : (w == 1) ? D1 : D2;
  const int lane = idx & 31;
  const int kb = (idx >> 5) & 1;
  const int n8 = (idx >> 6) & 15;
  const int kt = (idx >> 10) & 63;
  const int nb = idx >> 16;                          // 0..7
  const int k0 = kt * 16 + kb * 8 + (lane & 3);
  const int c  = nb * 128 + n8 * 8 + (lane >> 2);
  float2 o;
  o.x = tf32_rna(W[(size_t)k0 * 1024 + c]);
  o.y = tf32_rna(W[(size_t)(k0 + 4) * 1024 + c]);
  reinterpret_cast<float2*>(D)[idx] = o;
}

__global__ void pack_small_kernel(const float* __restrict__ bq,
                                  const float* __restrict__ bk,
                                  const float* __restrict__ bv,
                                  const float* __restrict__ fg_t,
                                  const float* __restrict__ fg_v,
                                  const float* __restrict__ bg_t,
                                  const float* __restrict__ bg_v,
                                  float* __restrict__ bp,
                                  float* __restrict__ tg) {
  const int i = blockIdx.x * 256 + threadIdx.x;
  if (i < 1024) {
    bp[i] = bq[i]; bp[1024 + i] = bk[i]; bp[2048 + i] = bv[i];
    tg[i]        = tanhf(fg_t[i]);
    tg[1024 + i] = tanhf(fg_v[i]);
    tg[2048 + i] = tanhf(bg_t[i]);
    tg[3072 + i] = tanhf(bg_v[i]);
  }
}

// ---------------------------------------------------------------------------
// Common GEMM mainloop (GBK=32, 3-stage cp.async, dyn smem)
// ---------------------------------------------------------------------------
#define GEMM_SMEM (6 * 4096 * 4)

#define GEMM_MAINLOOP(Abase, Bbase)                                            \
  float acc[2][8][4];                                                          \
  _Pragma("unroll")                                                            \
  for (int mi = 0; mi < 2; mi++)                                               \
    _Pragma("unroll")                                                          \
    for (int ni = 0; ni < 8; ni++)                                             \
      _Pragma("unroll")                                                        \
      for (int j = 0; j < 4; j++) acc[mi][ni][j] = 0.f;                        \
  auto issue = [&](int kt2, int s) {                                           \
    const float* ga = (Abase) + (size_t)kt2 * 4096;                            \
    const float* gb = (Bbase) + (size_t)kt2 * 4096;                            \
    const uint32_t da = sA + s * 16384 + tid * 16;                             \
    const uint32_t db = sB + s * 16384 + tid * 16;                             \
    cp16(da,         ga + tid * 4);                                            \
    cp16(da + 4096,  ga + 1024 + tid * 4);                                     \
    cp16(da + 8192,  ga + 2048 + tid * 4);                                     \
    cp16(da + 12288, ga + 3072 + tid * 4);                                     \
    cp16(db,         gb + tid * 4);                                            \
    cp16(db + 4096,  gb + 1024 + tid * 4);                                     \
    cp16(db + 8192,  gb + 2048 + tid * 4);                                     \
    cp16(db + 12288, gb + 3072 + tid * 4);                                     \
    asm volatile("cp.async.commit_group;");                                    \
  };                                                                           \
  issue(0, 0);                                                                 \
  issue(1, 1);                                                                 \
  int s = 0;                                                                   \
  for (int t = 0; t < 32; t++) {                                               \
    if (t < 30) { asm volatile("cp.async.wait_group 1;"); }                    \
    else        { asm volatile("cp.async.wait_group 0;"); }                    \
    __syncthreads();                                                           \
    if (t + 2 < 32) issue(t + 2, (t + 2) % 3);                                 \
    const float4* a4 = reinterpret_cast<const float4*>(As + s * 4096);         \
    const float2* b2 = reinterpret_cast<const float2*>(Bs + s * 4096);         \
    _Pragma("unroll")                                                          \
    for (int kb = 0; kb < 4; kb++) {                                           \
      const int half = kb >> 1;                                                \
      const int kbl  = kb & 1;                                                 \
      float4 af[2];                                                            \
      float2 bf[8];                                                            \
      _Pragma("unroll")                                                        \
      for (int mi = 0; mi < 2; mi++)                                           \
        af[mi] = a4[half * 512 + ((((ws << 1) + mi) * 2 + kbl) << 5) + lane];  \
      _Pragma("unroll")                                                        \
      for (int ni = 0; ni < 8; ni++)                                           \
        bf[ni] = b2[half * 1024 + ((((wn >> 3) + ni) * 2 + kbl) << 5) + lane]; \
      _Pragma("unroll")                                                        \
      for (int mi = 0; mi < 2; mi++) {                                         \
        const uint32_t a0 = __float_as_uint(af[mi].x);                         \
        const uint32_t a1 = __float_as_uint(af[mi].y);                         \
        const uint32_t a2 = __float_as_uint(af[mi].z);                         \
        const uint32_t a3 = __float_as_uint(af[mi].w);                         \
        _Pragma("unroll")                                                      \
        for (int ni = 0; ni < 8; ni++) {                                       \
          asm volatile(                                                        \
              "mma.sync.aligned.m16n8k8.row.col.f32.tf32.tf32.f32 "            \
              "{%0,%1,%2,%3}, {%4,%5,%6,%7}, {%8,%9}, {%0,%1,%2,%3};"          \
              : "+f"(acc[mi][ni][0]), "+f"(acc[mi][ni][1]),                    \
                "+f"(acc[mi][ni][2]), "+f"(acc[mi][ni][3])                     \
              : "r"(a0), "r"(a1), "r"(a2), "r"(a3),                            \
                "r"(__float_as_uint(bf[ni].x)),                                \
                "r"(__float_as_uint(bf[ni].y)));                               \
        }                                                                      \
      }                                                                        \
    }                                                                          \
    s = (s + 1) % 3;                                                           \
  }

// ---------------------------------------------------------------------------
// Generic GEMM (modes 0/1/2/3)
// ---------------------------------------------------------------------------
#define TSTRIDE 132
__global__ void __launch_bounds__(256) tf32_gemm_perm(
    const float* __restrict__ Ap, const float* __restrict__ Bp,
    const float* __restrict__ bias, float* __restrict__ C,
    int M, int N,
    const float* __restrict__ e_base, const float* __restrict__ tga,
    const float* __restrict__ tgb, int mode) {
  extern __shared__ float smg[];
  float* As = smg;
  float* Bs = smg + 12288;
  const int tid = threadIdx.x;
  const int warp = tid >> 5, lane = tid & 31;
  const int ws = warp & 3;
  const int wn = (warp >> 2) << 6;
  const int grp = lane >> 2, gcc = lane & 3;
  const int rb = blockIdx.y, nb = blockIdx.x;
  const uint32_t sA = (uint32_t)__cvta_generic_to_shared(As);
  const uint32_t sB = (uint32_t)__cvta_generic_to_shared(Bs);

  GEMM_MAINLOOP(Ap + (size_t)rb * 64 * 2048, Bp + (size_t)nb * 64 * 2048)

  const int row0 = rb * 128 + ws * 32;
  const int col0 = nb * 128 + wn;

  if (mode == 0) {
#pragma unroll
    for (int mi = 0; mi < 2; mi++) {
      const int row = row0 + mi * 16 + grp;
#pragma unroll
      for (int ni = 0; ni < 8; ni++) {
        const int col = col0 + ni * 8 + (gcc << 1);
        float b0 = 0.f, b1 = 0.f;
        if (bias) { b0 = __ldg(bias + col); b1 = __ldg(bias + col + 1); }
        if (row < M) {
          float2 o; o.x = acc[mi][ni][0] + b0; o.y = acc[mi][ni][1] + b1;
          *reinterpret_cast<float2*>(C + (size_t)row * N + col) = o;
        }
        if (row + 8 < M) {
          float2 o; o.x = acc[mi][ni][2] + b0; o.y = acc[mi][ni][3] + b1;
          *reinterpret_cast<float2*>(C + (size_t)(row + 8) * N + col) = o;
        }
      }
    }
  } else if (mode == 1) {
    float* revp = (float*)bias;
#pragma unroll
    for (int mi = 0; mi < 2; mi++) {
#pragma unroll
      for (int rr = 0; rr < 2; rr++) {
        const int row = row0 + mi * 16 + grp + rr * 8;
        if (row >= M) continue;
        const float* tg = (row < SEQ_TXT) ? tga : tgb;
        const int ri = rev_map(row);
#pragma unroll
        for (int ni = 0; ni < 8; ni++) {
          const int col = col0 + ni * 8 + (gcc << 1);
          const float2 e = *reinterpret_cast<const float2*>(e_base + (size_t)row * N + col);
          const float2 t = *reinterpret_cast<const float2*>(tg + col);
          float2 o;
          o.x = e.x + t.x * acc[mi][ni][rr * 2 + 0];
          o.y = e.y + t.y * acc[mi][ni][rr * 2 + 1];
          *reinterpret_cast<float2*>(C + (size_t)row * N + col) = o;
          revp[aperm_off(ri, col)]     = tf32_rna(o.x);
          revp[aperm_off(ri, col + 1)] = tf32_rna(o.y);
        }
      }
    }
  } else if (mode == 2) {
#pragma unroll
    for (int mi = 0; mi < 2; mi++) {
#pragma unroll
      for (int rr = 0; rr < 2; rr++) {
        const int row = row0 + mi * 16 + grp + rr * 8;
        if (row >= M) continue;
        const int i = rev_map(row);
        const int dst = (i < SEQ_TXT) ? (VID_LEN + i) : (i - SEQ_TXT);
        const float* tg = (i < SEQ_TXT) ? tga : tgb;
#pragma unroll
        for (int ni = 0; ni < 8; ni++) {
          const int col = col0 + ni * 8 + (gcc << 1);
          const float2 e = *reinterpret_cast<const float2*>(e_base + (size_t)i * N + col);
          const float2 t = *reinterpret_cast<const float2*>(tg + col);
          float2 o;
          o.x = e.x + t.x * acc[mi][ni][rr * 2 + 0];
          o.y = e.y + t.y * acc[mi][ni][rr * 2 + 1];
          *reinterpret_cast<float2*>(C + (size_t)dst * N + col) = o;
        }
      }
    }
  } else {
    __syncthreads();
    float* Ts = smg;
#pragma unroll
    for (int mi = 0; mi < 2; mi++) {
#pragma unroll
      for (int rr = 0; rr < 2; rr++) {
        const int trow = ws * 32 + mi * 16 + grp + rr * 8;
#pragma unroll
        for (int ni = 0; ni < 8; ni++) {
          const int tcol = wn + ni * 8 + (gcc << 1);
          Ts[trow * TSTRIDE + tcol]     = acc[mi][ni][rr * 2 + 0];
          Ts[trow * TSTRIDE + tcol + 1] = acc[mi][ni][rr * 2 + 1];
        }
      }
    }
    __syncthreads();
    if (tid < 128) {
      const int col = nb * 128 + tid;
      const float a = 1.f / (1.f + expf(-e_base[col]));
      const int t0 = rb * 128;
      const int t1 = (t0 + 128 < M) ? (t0 + 128) : M;
      float hv = 0.f;
      for (int t = t0; t < t1; t++) {
        hv = fmaf(a, hv, Ts[(t - t0) * TSTRIDE + tid]);
        Ts[(t - t0) * TSTRIDE + tid] = hv;
      }
      ((float*)tga)[rb * 1024 + col] = hv;   // raw per-chunk carry
    }
    __syncthreads();
    for (int ii = tid; ii < 4096; ii += 256) {
      const int l2   = ii & 31;
      const int half = (ii >> 5) & 1;
      const int gg   = (ii >> 6) & 7;
      const int ktl  = ii >> 9;
      const int rl = gg * 16 + (l2 >> 2);
      const int cl = ktl * 16 + half * 8 + (l2 & 3);
      float4 o;
      o.x = Ts[rl * TSTRIDE + cl];
      o.y = Ts[(rl + 8) * TSTRIDE + cl];
      o.z = Ts[rl * TSTRIDE + cl + 4];
      o.w = Ts[(rl + 8) * TSTRIDE + cl + 4];
      const size_t off = ((size_t)(rb * 64 + nb * 8 + ktl)) * 2048 +
                         (((gg << 1) + half) << 7) + (l2 << 2);
      *reinterpret_cast<float4*>(C + off) = o;
    }
  }
}

// ---------------------------------------------------------------------------
// QKV GEMM with fused layernorm+RoPE+transpose epilogue.
// ---------------------------------------------------------------------------
__global__ void __launch_bounds__(256) tf32_gemm_qkv(
    const float* __restrict__ Ap, const float* __restrict__ Bp,
    const float* __restrict__ bias,
    const float* __restrict__ qn_w, const float* __restrict__ qn_b,
    const float* __restrict__ kn_w, const float* __restrict__ kn_b,
    float* __restrict__ qt, float* __restrict__ kt, float* __restrict__ vt) {
  extern __shared__ float smg[];
  float* As = smg;
  float* Bs = smg + 12288;
  const int tid = threadIdx.x;
  const int warp = tid >> 5, lane = tid & 31;
  const int ws = warp & 3;
  const int wn = (warp >> 2) << 6;
  const int grp = lane >> 2, gcc = lane & 3;
  const int rb = blockIdx.y, nb = blockIdx.x;
  const uint32_t sA = (uint32_t)__cvta_generic_to_shared(As);
  const uint32_t sB = (uint32_t)__cvta_generic_to_shared(Bs);

  GEMM_MAINLOOP(Ap + (size_t)rb * 64 * 2048, Bp + (size_t)nb * 64 * 2048)

  __syncthreads();
  float* Ts = smg;
#pragma unroll
  for (int mi = 0; mi < 2; mi++) {
#pragma unroll
    for (int rr = 0; rr < 2; rr++) {
      const int trow = ws * 32 + mi * 16 + grp + rr * 8;
#pragma unroll
      for (int ni = 0; ni < 8; ni++) {
        const int tcol = wn + ni * 8 + (gcc << 1);
        const float b0 = __ldg(bias + nb * 128 + tcol);
        const float b1 = __ldg(bias + nb * 128 + tcol + 1);
        Ts[trow * TSTRIDE + tcol]     = acc[mi][ni][rr * 2 + 0] + b0;
        Ts[trow * TSTRIDE + tcol + 1] = acc[mi][ni][rr * 2 + 1] + b1;
      }
    }
  }
  __syncthreads();

  const int tr = tid >> 1;
  const int hl = tid & 1;
  const int row = rb * 128 + tr;
  if (row >= M_ATTN) return;
  const int bc = row / T_ATTN;
  const int t  = row - bc * T_ATTN;
  const int h  = ((nb & 7) << 1) + hl;
  float x[64];
#pragma unroll
  for (int d = 0; d < 64; d += 4) {
    const float4 v4 = *reinterpret_cast<const float4*>(&Ts[tr * TSTRIDE + hl * 64 + d]);
    x[d] = v4.x; x[d+1] = v4.y; x[d+2] = v4.z; x[d+3] = v4.w;
  }
  float* outb;
  if (nb < 16) {
    const float* nw = (nb < 8) ? qn_w : kn_w;
    const float* nbi = (nb < 8) ? qn_b : kn_b;
    float sm = 0.f, ss = 0.f;
#pragma unroll
    for (int d = 0; d < 64; d++) { sm += x[d]; ss += x[d] * x[d]; }
    const float mu  = sm * (1.f / 64.f);
    const float var = ss * (1.f / 64.f) - mu * mu;
    const float rr  = rsqrtf(var + 1e-6f);
#pragma unroll
    for (int d = 0; d < 64; d++) x[d] = (x[d] - mu) * rr * nw[d] + nbi[d];
    if (t >= TXT_LEN) rope_apply(x, t);
    outb = (nb < 8) ? qt : kt;
  } else {
    outb = vt;
  }
  const size_t dst = ((size_t)(bc * NHEAD + h) * T_ATTN + t) * HDIM;
#pragma unroll
  for (int d = 0; d < 64; d += 4)
    *reinterpret_cast<float4*>(outb + dst + d) =
        make_float4(tf32_rna(x[d]), tf32_rna(x[d+1]), tf32_rna(x[d+2]), tf32_rna(x[d+3]));
}

// ---------------------------------------------------------------------------
// Coalesced A-perm writers
// ---------------------------------------------------------------------------
__global__ void gather_cur_perm4(const float* __restrict__ vid,
                                 const float* __restrict__ txt,
                                 float* __restrict__ curp) {
  const int idx = blockIdx.x * 256 + threadIdx.x;
  const APermIdx ix = aperm_decode(idx);
  auto ld = [&](int r, int c) -> float {
    if (r >= M_ATTN) return 0.f;
    const int bc = r / T_ATTN;
    const int t  = r - bc * T_ATTN;
    return (t < TXT_LEN)
        ? txt[(size_t)(bc * TXT_LEN + t) * D_MODEL + c]
        : vid[(size_t)(bc * 768 + (t - TXT_LEN)) * D_MODEL + c];
  };
  float4 o;
  o.x = tf32_rna(ld(ix.r0,     ix.c0));
  o.y = tf32_rna(ld(ix.r0 + 8, ix.c0));
  o.z = tf32_rna(ld(ix.r0,     ix.c0 + 4));
  o.w = tf32_rna(ld(ix.r0 + 8, ix.c0 + 4));
  *reinterpret_cast<float4*>(curp + ix.off) = o;
}

// build_emb fused with perm: writes emb (row-major raw) and embp (perm tf32)
__global__ void build_emb_perm4(const float* __restrict__ proj,
                                float* __restrict__ emb,
                                float* __restrict__ embp) {
  const int idx = blockIdx.x * 256 + threadIdx.x;
  const APermIdx ix = aperm_decode(idx);
  auto combine = [&](int i, int c) -> float {
    if (i >= SEQ_SSM) return 0.f;
    if (i < SEQ_TXT) {
      const int ch = i / TXT_LEN;
      const int t  = i - ch * TXT_LEN;
      return proj[(size_t)(ch * SEG_PAD + t) * D_MODEL + c];
    }
    const int p = i - SEQ_TXT;
    float acc = 0.f; int cnt = 0;
#pragma unroll
    for (int ch = 0; ch < 4; ch++) {
      const int j = p - ch * 768;
      if (j >= 0 && j < CHUNK_VID) {
        acc += proj[(size_t)(ch * SEG_PAD + TXT_LEN + j) * D_MODEL + c];
        cnt++;
      }
    }
    return acc * (1.f / (float)cnt);
  };
  const float v00 = combine(ix.r0,     ix.c0);
  const float v10 = combine(ix.r0 + 8, ix.c0);
  const float v01 = combine(ix.r0,     ix.c0 + 4);
  const float v11 = combine(ix.r0 + 8, ix.c0 + 4);
  if (ix.r0 < SEQ_SSM) {
    emb[(size_t)ix.r0 * D_MODEL + ix.c0]     = v00;
    emb[(size_t)ix.r0 * D_MODEL + ix.c0 + 4] = v01;
  }
  if (ix.r0 + 8 < SEQ_SSM) {
    emb[(size_t)(ix.r0 + 8) * D_MODEL + ix.c0]     = v10;
    emb[(size_t)(ix.r0 + 8) * D_MODEL + ix.c0 + 4] = v11;
  }
  *reinterpret_cast<float4*>(embp + ix.off) =
      make_float4(tf32_rna(v00), tf32_rna(v10), tf32_rna(v01), tf32_rna(v11));
}

// ---------------------------------------------------------------------------
// Flash attention tf32, 128-row tiles, in-warp softmax (known good).
// ---------------------------------------------------------------------------
#define FS 68
#define FA_SMEM ((384 * FS) * 4)

__global__ void __launch_bounds__(256) flash_tf32_kernel(
    const float* __restrict__ Qt, const float* __restrict__ Kt,
    const float* __restrict__ Vt, float* __restrict__ Outp) {
  extern __shared__ float sm[];
  float* Qs = sm;
  float* Ks = sm + 128 * FS;
  float* Vs = sm + 192 * FS;
  float* Ss = sm + 256 * FS;

  const int mat = blockIdx.y;
  const int q0  = blockIdx.x * 128;
  const int tid = threadIdx.x;
  const int warp = tid >> 5;
  const int lane = tid & 31;
  const int gr = lane >> 2;
  const int gc = lane & 3;
  const int wm = warp * 16;

  const float* Qb = Qt + (size_t)mat * T_ATTN * HDIM;
  const float* Kb = Kt + (size_t)mat * T_ATTN * HDIM;
  const float* Vb = Vt + (size_t)mat * T_ATTN * HDIM;

  {
    const int r  = tid >> 1;
    const int d0 = (tid & 1) << 5;
    const int gq = q0 + r;
#pragma unroll
    for (int i = 0; i < 32; i += 4) {
      float4 v4 = make_float4(0.f, 0.f, 0.f, 0.f);
      if (gq < T_ATTN)
        v4 = *reinterpret_cast<const float4*>(Qb + (size_t)gq * HDIM + d0 + i);
      *reinterpret_cast<float4*>(&Qs[r * FS + d0 + i]) = v4;
    }
  }
  __syncthreads();

  uint32_t qf[8][4];
#pragma unroll
  for (int kb = 0; kb < 8; kb++) {
    const int base = (wm + gr) * FS + kb * 8 + gc;
    qf[kb][0] = __float_as_uint(Qs[base]);
    qf[kb][1] = __float_as_uint(Qs[base + 8 * FS]);
    qf[kb][2] = __float_as_uint(Qs[base + 4]);
    qf[kb][3] = __float_as_uint(Qs[base + 8 * FS + 4]);
  }
  __syncthreads();

  float acc[8][4];
#pragma unroll
  for (int ni = 0; ni < 8; ni++)
#pragma unroll
    for (int j = 0; j < 4; j++) acc[ni][j] = 0.f;

  float mrun0 = -1e30f, mrun1 = -1e30f;
  float lrun0 = 0.f, lrun1 = 0.f;

  for (int k0 = 0; k0 < T_ATTN; k0 += 64) {
    {
      const int r  = tid >> 2;
      const int d0 = (tid & 3) << 4;
      const int gk = k0 + r;
#pragma unroll
      for (int i = 0; i < 16; i += 4) {
        float4 kv = make_float4(0.f, 0.f, 0.f, 0.f);
        float4 vv = make_float4(0.f, 0.f, 0.f, 0.f);
        if (gk < T_ATTN) {
          kv = *reinterpret_cast<const float4*>(Kb + (size_t)gk * HDIM + d0 + i);
          vv = *reinterpret_cast<const float4*>(Vb + (size_t)gk * HDIM + d0 + i);
        }
        *reinterpret_cast<float4*>(&Ks[r * FS + d0 + i]) = kv;
        *reinterpret_cast<float4*>(&Vs[r * FS + d0 + i]) = vv;
      }
    }
    __syncthreads();

    float sacc[8][4];
#pragma unroll
    for (int ni = 0; ni < 8; ni++)
#pragma unroll
      for (int j = 0; j < 4; j++) sacc[ni][j] = 0.f;
#pragma unroll
    for (int kb = 0; kb < 8; kb++) {
      uint32_t bf[8][2];
#pragma unroll
      for (int ni = 0; ni < 8; ni++) {
        const int kbase = (ni * 8 + gr) * FS + kb * 8 + gc;
        bf[ni][0] = __float_as_uint(Ks[kbase]);
        bf[ni][1] = __float_as_uint(Ks[kbase + 4]);
      }
#pragma unroll
      for (int ni = 0; ni < 8; ni++) {
        asm volatile(
            "mma.sync.aligned.m16n8k8.row.col.f32.tf32.tf32.f32 "
            "{%0,%1,%2,%3}, {%4,%5,%6,%7}, {%8,%9}, {%0,%1,%2,%3};"
            : "+f"(sacc[ni][0]), "+f"(sacc[ni][1]),
              "+f"(sacc[ni][2]), "+f"(sacc[ni][3])
            : "r"(qf[kb][0]), "r"(qf[kb][1]), "r"(qf[kb][2]), "r"(qf[kb][3]),
              "r"(bf[ni][0]), "r"(bf[ni][1]));
      }
    }

    float m0 = -1e30f, m1 = -1e30f;
#pragma unroll
    for (int ni = 0; ni < 8; ni++) {
      const int gk = k0 + ni * 8 + (gc << 1);
      sacc[ni][0] = (gk     < T_ATTN) ? sacc[ni][0] * ATTN_SCALE : -1e30f;
      sacc[ni][1] = (gk + 1 < T_ATTN) ? sacc[ni][1] * ATTN_SCALE : -1e30f;
      sacc[ni][2] = (gk     < T_ATTN) ? sacc[ni][2] * ATTN_SCALE : -1e30f;
      sacc[ni][3] = (gk + 1 < T_ATTN) ? sacc[ni][3] * ATTN_SCALE : -1e30f;
      m0 = fmaxf(m0, fmaxf(sacc[ni][0], sacc[ni][1]));
      m1 = fmaxf(m1, fmaxf(sacc[ni][2], sacc[ni][3]));
    }
    m0 = fmaxf(m0, __shfl_xor_sync(0xffffffffu, m0, 1));
    m0 = fmaxf(m0, __shfl_xor_sync(0xffffffffu, m0, 2));
    m1 = fmaxf(m1, __shfl_xor_sync(0xffffffffu, m1, 1));
    m1 = fmaxf(m1, __shfl_xor_sync(0xffffffffu, m1, 2));
    const float mn0 = fmaxf(mrun0, m0);
    const float mn1 = fmaxf(mrun1, m1);
    const float sc0 = __expf(mrun0 - mn0);
    const float sc1 = __expf(mrun1 - mn1);
    mrun0 = mn0; mrun1 = mn1;

    float s0 = 0.f, s1 = 0.f;
#pragma unroll
    for (int ni = 0; ni < 8; ni++) {
      sacc[ni][0] = tf32_rna(__expf(sacc[ni][0] - mn0));
      sacc[ni][1] = tf32_rna(__expf(sacc[ni][1] - mn0));
      sacc[ni][2] = tf32_rna(__expf(sacc[ni][2] - mn1));
      sacc[ni][3] = tf32_rna(__expf(sacc[ni][3] - mn1));
      s0 += sacc[ni][0] + sacc[ni][1];
      s1 += sacc[ni][2] + sacc[ni][3];
    }
    s0 += __shfl_xor_sync(0xffffffffu, s0, 1);
    s0 += __shfl_xor_sync(0xffffffffu, s0, 2);
    s1 += __shfl_xor_sync(0xffffffffu, s1, 1);
    s1 += __shfl_xor_sync(0xffffffffu, s1, 2);
    lrun0 = lrun0 * sc0 + s0;
    lrun1 = lrun1 * sc1 + s1;

#pragma unroll
    for (int ni = 0; ni < 8; ni++) {
      const int col = ni * 8 + (gc << 1);
      *reinterpret_cast<float2*>(&Ss[(wm + gr) * FS + col]) =
          make_float2(sacc[ni][0], sacc[ni][1]);
      *reinterpret_cast<float2*>(&Ss[(wm + 8 + gr) * FS + col]) =
          make_float2(sacc[ni][2], sacc[ni][3]);
    }
    __syncwarp();

#pragma unroll
    for (int ni = 0; ni < 8; ni++) {
      acc[ni][0] *= sc0; acc[ni][1] *= sc0;
      acc[ni][2] *= sc1; acc[ni][3] *= sc1;
    }
#pragma unroll
    for (int kb = 0; kb < 8; kb++) {
      uint32_t af[4];
      const int abase = (wm + gr) * FS + kb * 8 + gc;
      af[0] = __float_as_uint(Ss[abase]);
      af[1] = __float_as_uint(Ss[abase + 8 * FS]);
      af[2] = __float_as_uint(Ss[abase + 4]);
      af[3] = __float_as_uint(Ss[abase + 8 * FS + 4]);
      uint32_t bf[8][2];
#pragma unroll
      for (int ni = 0; ni < 8; ni++) {
        const int vbase = (kb * 8 + gc) * FS + ni * 8 + gr;
        bf[ni][0] = __float_as_uint(Vs[vbase]);
        bf[ni][1] = __float_as_uint(Vs[vbase + 4 * FS]);
      }
#pragma unroll
      for (int ni = 0; ni < 8; ni++) {
        asm volatile(
            "mma.sync.aligned.m16n8k8.row.col.f32.tf32.tf32.f32 "
            "{%0,%1,%2,%3}, {%4,%5,%6,%7}, {%8,%9}, {%0,%1,%2,%3};"
            : "+f"(acc[ni][0]), "+f"(acc[ni][1]),
              "+f"(acc[ni][2]), "+f"(acc[ni][3])
            : "r"(af[0]), "r"(af[1]), "r"(af[2]), "r"(af[3]),
              "r"(bf[ni][0]), "r"(bf[ni][1]));
      }
    }
    __syncthreads();
  }

  {
    const float inv0 = 1.f / lrun0;
    const float inv1 = 1.f / lrun1;
#pragma unroll
    for (int ni = 0; ni < 8; ni++) {
      const int col = ni * 8 + (gc << 1);
      Ss[(wm + gr) * FS + col]         = acc[ni][0] * inv0;
      Ss[(wm + gr) * FS + col + 1]     = acc[ni][1] * inv0;
      Ss[(wm + 8 + gr) * FS + col]     = acc[ni][2] * inv1;
      Ss[(wm + 8 + gr) * FS + col + 1] = acc[ni][3] * inv1;
    }
  }
  __syncthreads();
  {
    const int bc = mat >> 4;
    const int h  = mat & 15;
    const int rb = (bc * SEG_PAD + q0) >> 7;
    for (int ii = tid; ii < 2048; ii += 256) {
      const int l2   = ii & 31;
      const int half = (ii >> 5) & 1;
      const int ktl  = (ii >> 6) & 3;
      const int gg   = (ii >> 8) & 7;
      const int rl = gg * 16 + (l2 >> 2);
      const int cl = ktl * 16 + half * 8 + (l2 & 3);
      float4 o;
      o.x = tf32_rna(Ss[rl * FS + cl]);
      o.y = tf32_rna(Ss[(rl + 8) * FS + cl]);
      o.z = tf32_rna(Ss[rl * FS + cl + 4]);
      o.w = tf32_rna(Ss[(rl + 8) * FS + cl + 4]);
      const int kt = h * 4 + ktl;
      const size_t off = ((size_t)(rb * 64 + kt)) * 2048 +
                         (((gg << 1) + half) << 7) + (l2 << 2);
      *reinterpret_cast<float4*>(Outp + off) = o;
    }
  }
}

// ---------------------------------------------------------------------------
// SSM scan pass3 (carry prefix computed inline; pass2 eliminated)
// ---------------------------------------------------------------------------
__global__ void scan_pass3_perm4(const float* __restrict__ hlocp,
                                 const float* __restrict__ gate,
                                 const float* __restrict__ carry,
                                 float* __restrict__ hp) {
  const int idx = blockIdx.x * 256 + threadIdx.x;
  const APermIdx ix = aperm_decode(idx);
  const int chunk = ix.r0 >> 7;
  const int t0 = chunk << 7;
  const float a0 = 1.f / (1.f + expf(-gate[ix.c0]));
  const float a1 = 1.f / (1.f + expf(-gate[ix.c0 + 4]));
  const float a128_0 = __powf(a0, 128.f);
  const float a128_1 = __powf(a1, 128.f);
  float cin0 = 0.f, cin1 = 0.f;
  for (int c = 0; c < chunk; c++) {
    cin0 = a128_0 * cin0 + carry[c * 1024 + ix.c0];
    cin1 = a128_1 * cin1 + carry[c * 1024 + ix.c0 + 4];
  }
  const float e = (float)(ix.r0 - t0 + 1);
  const float p0  = __powf(a0, e);
  const float p1  = __powf(a1, e);
  const float p0b = p0 * __powf(a0, 8.f);
  const float p1b = p1 * __powf(a1, 8.f);
  const float4 v = *reinterpret_cast<const float4*>(hlocp + ix.off);
  float4 o;
  o.x = (ix.r0     < SEQ_SSM) ? tf32_rna(v.x + p0  * cin0) : 0.f;
  o.y = (ix.r0 + 8 < SEQ_SSM) ? tf32_rna(v.y + p0b * cin0) : 0.f;
  o.z = (ix.r0     < SEQ_SSM) ? tf32_rna(v.z + p1  * cin1) : 0.f;
  o.w = (ix.r0 + 8 < SEQ_SSM) ? tf32_rna(v.w + p1b * cin1) : 0.f;
  *reinterpret_cast<float4*>(hp + ix.off) = o;
}

// ---------------------------------------------------------------------------
// Launch
// ---------------------------------------------------------------------------
static float* sym_addr(const void* symbol) {
  void* p = nullptr;
  cudaGetSymbolAddress(&p, symbol);
  return (float*)p;
}

extern "C" void kernel_launch(void* const* d_in, const int* in_sizes, int n_in,
                              void* d_out, int out_size) {
  (void)in_sizes; (void)n_in; (void)out_size;
  const float* vid   = (const float*)d_in[0];
  const float* txt   = (const float*)d_in[1];
  const float* Wq    = (const float*)d_in[2];
  const float* bq    = (const float*)d_in[3];
  const float* Wk    = (const float*)d_in[4];
  const float* bk    = (const float*)d_in[5];
  const float* Wv    = (const float*)d_in[6];
  const float* bv    = (const float*)d_in[7];
  const float* Wo    = (const float*)d_in[8];
  const float* bo    = (const float*)d_in[9];
  const float* qn_w  = (const float*)d_in[10];
  const float* qn_b  = (const float*)d_in[11];
  const float* kn_w  = (const float*)d_in[12];
  const float* kn_b  = (const float*)d_in[13];
  const float* Win   = (const float*)d_in[14];
  const float* Wout  = (const float*)d_in[15];
  const float* gate  = (const float*)d_in[16];
  const float* fg_t  = (const float*)d_in[17];
  const float* fg_v  = (const float*)d_in[18];
  const float* bg_t  = (const float*)d_in[19];
  const float* bg_v  = (const float*)d_in[20];
  float* out = (float*)d_out;

  float* curp  = sym_addr(g_curp);
  float* qt    = sym_addr(g_qt);
  float* kt    = sym_addr(g_kt);
  float* vt    = sym_addr(g_vt);
  float* attnp = sym_addr(g_attnp);
  float* proj  = sym_addr(g_proj);
  float* emb   = sym_addr(g_emb);
  float* embp  = sym_addr(g_embp);
  float* hlocp = sym_addr(g_hlocp);
  float* hp    = sym_addr(g_hp);
  float* emb2  = sym_addr(g_emb2);
  float* revp  = sym_addr(g_revp);
  float* carry = sym_addr(g_carry);
  float* wqkv  = sym_addr(g_wqkv);
  float* bqkv  = sym_addr(g_bqkv);
  float* wo_p  = sym_addr(g_wo);
  float* win_p  = sym_addr(g_win);
  float* wout_p = sym_addr(g_wout);
  float* tg     = sym_addr(g_tg);

  cudaFuncSetAttribute(flash_tf32_kernel, cudaFuncAttributeMaxDynamicSharedMemorySize, FA_SMEM);
  cudaFuncSetAttribute(tf32_gemm_perm, cudaFuncAttributeMaxDynamicSharedMemorySize, GEMM_SMEM);
  cudaFuncSetAttribute(tf32_gemm_qkv, cudaFuncAttributeMaxDynamicSharedMemorySize, GEMM_SMEM);

  pack_qkv_perm2<<<6144, 256>>>(Wq, Wk, Wv, wqkv);
  pack_small_kernel<<<4, 256>>>(bq, bk, bv, fg_t, fg_v, bg_t, bg_v, bqkv, tg);
  pack3_b_perm2<<<6144, 256>>>(Wo, Win, Wout, wo_p, win_p, wout_p);

  gather_cur_perm4<<<5120, 256>>>(vid, txt, curp);
  tf32_gemm_qkv<<<dim3(24, 40), 256, GEMM_SMEM>>>(
      curp, wqkv, bqkv, qn_w, qn_b, kn_w, kn_b, qt, kt, vt);
  flash_tf32_kernel<<<dim3(10, 64), 256, FA_SMEM>>>(qt, kt, vt, attnp);
  tf32_gemm_perm<<<dim3(8, 40), 256, GEMM_SMEM>>>(
      attnp, wo_p, bo, proj, M_PAD, 1024, nullptr, nullptr, nullptr, 0);
  build_emb_perm4<<<4352, 256>>>(proj, emb, embp);

  // forward SSM (Win GEMM + local scan fused; pass3 computes carry prefix)
  tf32_gemm_perm<<<dim3(8, 34), 256, GEMM_SMEM>>>(
      embp, win_p, nullptr, hlocp, SEQ_SSM, 1024, gate, carry, nullptr, 3);
  scan_pass3_perm4<<<4352, 256>>>(hlocp, gate, carry, hp);
  tf32_gemm_perm<<<dim3(8, 34), 256, GEMM_SMEM>>>(
      hp, wout_p, revp, emb2, SEQ_SSM, 1024, emb, tg, tg + 1024, 1);

  // backward SSM
  tf32_gemm_perm<<<dim3(8, 34), 256, GEMM_SMEM>>>(
      revp, win_p, nullptr, hlocp, SEQ_SSM, 1024, gate, carry, nullptr, 3);
  scan_pass3_perm4<<<4352, 256>>>(hlocp, gate, carry, hp);
  tf32_gemm_perm<<<dim3(8, 34), 256, GEMM_SMEM>>>(
      hp, wout_p, nullptr, out, SEQ_SSM, 1024, emb2, tg + 2048, tg + 3072, 2);
}

// round 17
// speedup vs baseline: 1.0161x; 1.0161x over previous
#include <cuda_runtime.h>
#include <cuda_bf16.h>
#include <cstdint>

// ---------------------------------------------------------------------------
// Problem constants
// ---------------------------------------------------------------------------
#define D_MODEL 1024
#define NHEAD   16
#define HDIM    64
#define TXT_LEN 226
#define CHUNKS  4
#define SEQ_TXT 904
#define VID_LEN 3328
#define CHUNK_VID 1024
#define T_ATTN  1250
#define SEG_PAD 1280
#define M_ATTN  5000
#define M_PAD   5120
#define SEQ_SSM 4232
#define ATTN_SCALE 0.125f
#define NCHUNK  34

// ---------------------------------------------------------------------------
// Scratch (static __device__)
// ---------------------------------------------------------------------------
__device__ float g_curp [5242880];
__device__ float g_qt   [5120000];
__device__ float g_kt   [5120000];
__device__ float g_vt   [5120000];
__device__ float g_attnp[5242880];
__device__ float g_proj [5242880];
__device__ float g_emb  [4333568];
__device__ float g_embp [4456448];
__device__ float g_hlocp[4456448];
__device__ float g_hp   [4456448];
__device__ float g_emb2 [4333568];
__device__ float g_revp [4456448];
__device__ float g_carry[34816];
__device__ float g_wqkv[3145728];
__device__ float g_bqkv[3072];
__device__ float g_wo  [1048576];
__device__ float g_win [1048576];
__device__ float g_wout[1048576];
__device__ float g_tg  [4096];

__device__ __forceinline__ float tf32_rna(float x) {
  float r;
  asm("cvt.rna.tf32.f32 %0, %1;" : "=f"(r) : "f"(x));
  return r;
}

__device__ __forceinline__ size_t aperm_off(int r, int c) {
  const int rb = r >> 7, rl = r & 127;
  const int kt = c >> 4, cl = c & 15;
  const int g  = rl >> 4;
  const int j  = ((rl >> 3) & 1) | (((cl >> 2) & 1) << 1);
  const int lane = ((rl & 7) << 2) | (cl & 3);
  return ((size_t)(rb * 64 + kt)) * 2048 + (((g << 1) + (cl >> 3)) << 7) +
         (lane << 2) + j;
}

struct APermIdx { int r0, c0; size_t off; };
__device__ __forceinline__ APermIdx aperm_decode(int idx) {
  const int lane = idx & 31;
  const int half = (idx >> 5) & 1;
  const int g    = (idx >> 6) & 7;
  const int kt   = (idx >> 9) & 63;
  const int rb   = idx >> 15;
  APermIdx o;
  o.r0  = rb * 128 + g * 16 + (lane >> 2);
  o.c0  = kt * 16 + half * 8 + (lane & 3);
  o.off = ((size_t)(rb * 64 + kt)) * 2048 + (((g << 1) + half) << 7) + (lane << 2);
  return o;
}

__device__ __forceinline__ void cp16(uint32_t s, const void* g) {
  asm volatile("cp.async.cg.shared.global [%0], [%1], 16;" :: "r"(s), "l"(g));
}

__device__ __forceinline__ int rev_map(int i) {
  if (i < SEQ_TXT) {
    const int c = i / TXT_LEN;
    return (3 - c) * TXT_LEN + (i - c * TXT_LEN);
  }
  return 5135 - i;
}

__device__ __forceinline__ void rope_apply(float* x, int t) {
  const int p = t - TXT_LEN;
  const float fpos = (float)(p >> 8);
  const int rem = p & 255;
  const float hpos = (float)(rem >> 4);
  const float wpos = (float)(rem & 15);
#pragma unroll
  for (int i = 0; i < 8; i++) {
    const float ang = fpos * __powf(10000.f, -(float)i * 0.125f);
    float sn, cs; sincosf(ang, &sn, &cs);
    const float x1 = x[i], x2 = x[8 + i];
    x[i]     = x1 * cs - x2 * sn;
    x[8 + i] = x1 * sn + x2 * cs;
  }
#pragma unroll
  for (int i = 0; i < 12; i++) {
    const float ang = hpos * __powf(10000.f, -(float)i * (1.f / 12.f));
    float sn, cs; sincosf(ang, &sn, &cs);
    const float x1 = x[16 + i], x2 = x[28 + i];
    x[16 + i] = x1 * cs - x2 * sn;
    x[28 + i] = x1 * sn + x2 * cs;
  }
#pragma unroll
  for (int i = 0; i < 12; i++) {
    const float ang = wpos * __powf(10000.f, -(float)i * (1.f / 12.f));
    float sn, cs; sincosf(ang, &sn, &cs);
    const float x1 = x[40 + i], x2 = x[52 + i];
    x[40 + i] = x1 * cs - x2 * sn;
    x[52 + i] = x1 * sn + x2 * cs;
  }
}

// ---------------------------------------------------------------------------
// Weight packing — coalesced float2 bperm writers.
// ---------------------------------------------------------------------------
__global__ void pack_qkv_perm2(const float* __restrict__ Wq,
                               const float* __restrict__ Wk,
                               const float* __restrict__ Wv,
                               float* __restrict__ dst) {
  const int idx = blockIdx.x * 256 + threadIdx.x;
  const int lane = idx & 31;
  const int kb = (idx >> 5) & 1;
  const int n8 = (idx >> 6) & 15;
  const int kt = (idx >> 10) & 63;
  const int nb = idx >> 16;
  const int k0 = kt * 16 + kb * 8 + (lane & 3);
  const int cg = nb * 128 + n8 * 8 + (lane >> 2);
  const float* W = (cg < 1024) ? Wq : (cg < 2048) ? Wk : Wv;
  const int c = cg & 1023;
  float2 o;
  o.x = tf32_rna(W[(size_t)k0 * 1024 + c]);
  o.y = tf32_rna(W[(size_t)(k0 + 4) * 1024 + c]);
  reinterpret_cast<float2*>(dst)[idx] = o;
}

__global__ void pack3_b_perm2(const float* __restrict__ W0,
                              const float* __restrict__ W1,
                              const float* __restrict__ W2,
                              float* __restrict__ D0,
                              float* __restrict__ D1,
                              float* __restrict__ D2) {
  const int gidx = blockIdx.x * 256 + threadIdx.x;
  const int w  = gidx >> 19;
  const int idx = gidx & 524287;
  const float* W = (w == 0) ? W0 : (w == 1) ? W1 : W2;
  float* D       = (w == 0) ? D0 : (w == 1) ? D1 : D2;
  const int lane = idx & 31;
  const int kb = (idx >> 5) & 1;
  const int n8 = (idx >> 6) & 15;
  const int kt = (idx >> 10) & 63;
  const int nb = idx >> 16;
  const int k0 = kt * 16 + kb * 8 + (lane & 3);
  const int c  = nb * 128 + n8 * 8 + (lane >> 2);
  float2 o;
  o.x = tf32_rna(W[(size_t)k0 * 1024 + c]);
  o.y = tf32_rna(W[(size_t)(k0 + 4) * 1024 + c]);
  reinterpret_cast<float2*>(D)[idx] = o;
}

__global__ void pack_small_kernel(const float* __restrict__ bq,
                                  const float* __restrict__ bk,
                                  const float* __restrict__ bv,
                                  const float* __restrict__ fg_t,
                                  const float* __restrict__ fg_v,
                                  const float* __restrict__ bg_t,
                                  const float* __restrict__ bg_v,
                                  float* __restrict__ bp,
                                  float* __restrict__ tg) {
  const int i = blockIdx.x * 256 + threadIdx.x;
  if (i < 1024) {
    bp[i] = bq[i]; bp[1024 + i] = bk[i]; bp[2048 + i] = bv[i];
    tg[i]        = tanhf(fg_t[i]);
    tg[1024 + i] = tanhf(fg_v[i]);
    tg[2048 + i] = tanhf(bg_t[i]);
    tg[3072 + i] = tanhf(bg_v[i]);
  }
}

// ---------------------------------------------------------------------------
// Common GEMM mainloop (GBK=32, 3-stage cp.async, dyn smem)
// ---------------------------------------------------------------------------
#define GEMM_SMEM (6 * 4096 * 4)

#define GEMM_MAINLOOP(Abase, Bbase)                                            \
  float acc[2][8][4];                                                          \
  _Pragma("unroll")                                                            \
  for (int mi = 0; mi < 2; mi++)                                               \
    _Pragma("unroll")                                                          \
    for (int ni = 0; ni < 8; ni++)                                             \
      _Pragma("unroll")                                                        \
      for (int j = 0; j < 4; j++) acc[mi][ni][j] = 0.f;                        \
  auto issue = [&](int kt2, int s) {                                           \
    const float* ga = (Abase) + (size_t)kt2 * 4096;                            \
    const float* gb = (Bbase) + (size_t)kt2 * 4096;                            \
    const uint32_t da = sA + s * 16384 + tid * 16;                             \
    const uint32_t db = sB + s * 16384 + tid * 16;                             \
    cp16(da,         ga + tid * 4);                                            \
    cp16(da + 4096,  ga + 1024 + tid * 4);                                     \
    cp16(da + 8192,  ga + 2048 + tid * 4);                                     \
    cp16(da + 12288, ga + 3072 + tid * 4);                                     \
    cp16(db,         gb + tid * 4);                                            \
    cp16(db + 4096,  gb + 1024 + tid * 4);                                     \
    cp16(db + 8192,  gb + 2048 + tid * 4);                                     \
    cp16(db + 12288, gb + 3072 + tid * 4);                                     \
    asm volatile("cp.async.commit_group;");                                    \
  };                                                                           \
  issue(0, 0);                                                                 \
  issue(1, 1);                                                                 \
  int s = 0;                                                                   \
  for (int t = 0; t < 32; t++) {                                               \
    if (t < 30) { asm volatile("cp.async.wait_group 1;"); }                    \
    else        { asm volatile("cp.async.wait_group 0;"); }                    \
    __syncthreads();                                                           \
    if (t + 2 < 32) issue(t + 2, (t + 2) % 3);                                 \
    const float4* a4 = reinterpret_cast<const float4*>(As + s * 4096);         \
    const float2* b2 = reinterpret_cast<const float2*>(Bs + s * 4096);         \
    _Pragma("unroll")                                                          \
    for (int kb = 0; kb < 4; kb++) {                                           \
      const int half = kb >> 1;                                                \
      const int kbl  = kb & 1;                                                 \
      float4 af[2];                                                            \
      float2 bf[8];                                                            \
      _Pragma("unroll")                                                        \
      for (int mi = 0; mi < 2; mi++)                                           \
        af[mi] = a4[half * 512 + ((((ws << 1) + mi) * 2 + kbl) << 5) + lane];  \
      _Pragma("unroll")                                                        \
      for (int ni = 0; ni < 8; ni++)                                           \
        bf[ni] = b2[half * 1024 + ((((wn >> 3) + ni) * 2 + kbl) << 5) + lane]; \
      _Pragma("unroll")                                                        \
      for (int mi = 0; mi < 2; mi++) {                                         \
        const uint32_t a0 = __float_as_uint(af[mi].x);                         \
        const uint32_t a1 = __float_as_uint(af[mi].y);                         \
        const uint32_t a2 = __float_as_uint(af[mi].z);                         \
        const uint32_t a3 = __float_as_uint(af[mi].w);                         \
        _Pragma("unroll")                                                      \
        for (int ni = 0; ni < 8; ni++) {                                       \
          asm volatile(                                                        \
              "mma.sync.aligned.m16n8k8.row.col.f32.tf32.tf32.f32 "            \
              "{%0,%1,%2,%3}, {%4,%5,%6,%7}, {%8,%9}, {%0,%1,%2,%3};"          \
              : "+f"(acc[mi][ni][0]), "+f"(acc[mi][ni][1]),                    \
                "+f"(acc[mi][ni][2]), "+f"(acc[mi][ni][3])                     \
              : "r"(a0), "r"(a1), "r"(a2), "r"(a3),                            \
                "r"(__float_as_uint(bf[ni].x)),                                \
                "r"(__float_as_uint(bf[ni].y)));                               \
        }                                                                      \
      }                                                                        \
    }                                                                          \
    s = (s + 1) % 3;                                                           \
  }

// ---------------------------------------------------------------------------
// Generic GEMM (modes 0/1/2/3)
// ---------------------------------------------------------------------------
#define TSTRIDE 132
__global__ void __launch_bounds__(256) tf32_gemm_perm(
    const float* __restrict__ Ap, const float* __restrict__ Bp,
    const float* __restrict__ bias, float* __restrict__ C,
    int M, int N,
    const float* __restrict__ e_base, const float* __restrict__ tga,
    const float* __restrict__ tgb, int mode) {
  extern __shared__ float smg[];
  float* As = smg;
  float* Bs = smg + 12288;
  const int tid = threadIdx.x;
  const int warp = tid >> 5, lane = tid & 31;
  const int ws = warp & 3;
  const int wn = (warp >> 2) << 6;
  const int grp = lane >> 2, gcc = lane & 3;
  const int rb = blockIdx.y, nb = blockIdx.x;
  const uint32_t sA = (uint32_t)__cvta_generic_to_shared(As);
  const uint32_t sB = (uint32_t)__cvta_generic_to_shared(Bs);

  GEMM_MAINLOOP(Ap + (size_t)rb * 64 * 2048, Bp + (size_t)nb * 64 * 2048)

  const int row0 = rb * 128 + ws * 32;
  const int col0 = nb * 128 + wn;

  if (mode == 0) {
#pragma unroll
    for (int mi = 0; mi < 2; mi++) {
      const int row = row0 + mi * 16 + grp;
#pragma unroll
      for (int ni = 0; ni < 8; ni++) {
        const int col = col0 + ni * 8 + (gcc << 1);
        float b0 = 0.f, b1 = 0.f;
        if (bias) { b0 = __ldg(bias + col); b1 = __ldg(bias + col + 1); }
        if (row < M) {
          float2 o; o.x = acc[mi][ni][0] + b0; o.y = acc[mi][ni][1] + b1;
          *reinterpret_cast<float2*>(C + (size_t)row * N + col) = o;
        }
        if (row + 8 < M) {
          float2 o; o.x = acc[mi][ni][2] + b0; o.y = acc[mi][ni][3] + b1;
          *reinterpret_cast<float2*>(C + (size_t)(row + 8) * N + col) = o;
        }
      }
    }
  } else if (mode == 1) {
    float* revp = (float*)bias;
#pragma unroll
    for (int mi = 0; mi < 2; mi++) {
#pragma unroll
      for (int rr = 0; rr < 2; rr++) {
        const int row = row0 + mi * 16 + grp + rr * 8;
        if (row >= M) continue;
        const float* tg = (row < SEQ_TXT) ? tga : tgb;
        const int ri = rev_map(row);
#pragma unroll
        for (int ni = 0; ni < 8; ni++) {
          const int col = col0 + ni * 8 + (gcc << 1);
          const float2 e = *reinterpret_cast<const float2*>(e_base + (size_t)row * N + col);
          const float2 t = *reinterpret_cast<const float2*>(tg + col);
          float2 o;
          o.x = e.x + t.x * acc[mi][ni][rr * 2 + 0];
          o.y = e.y + t.y * acc[mi][ni][rr * 2 + 1];
          *reinterpret_cast<float2*>(C + (size_t)row * N + col) = o;
          revp[aperm_off(ri, col)]     = tf32_rna(o.x);
          revp[aperm_off(ri, col + 1)] = tf32_rna(o.y);
        }
      }
    }
  } else if (mode == 2) {
#pragma unroll
    for (int mi = 0; mi < 2; mi++) {
#pragma unroll
      for (int rr = 0; rr < 2; rr++) {
        const int row = row0 + mi * 16 + grp + rr * 8;
        if (row >= M) continue;
        const int i = rev_map(row);
        const int dst = (i < SEQ_TXT) ? (VID_LEN + i) : (i - SEQ_TXT);
        const float* tg = (i < SEQ_TXT) ? tga : tgb;
#pragma unroll
        for (int ni = 0; ni < 8; ni++) {
          const int col = col0 + ni * 8 + (gcc << 1);
          const float2 e = *reinterpret_cast<const float2*>(e_base + (size_t)i * N + col);
          const float2 t = *reinterpret_cast<const float2*>(tg + col);
          float2 o;
          o.x = e.x + t.x * acc[mi][ni][rr * 2 + 0];
          o.y = e.y + t.y * acc[mi][ni][rr * 2 + 1];
          *reinterpret_cast<float2*>(C + (size_t)dst * N + col) = o;
        }
      }
    }
  } else {
    __syncthreads();
    float* Ts = smg;
#pragma unroll
    for (int mi = 0; mi < 2; mi++) {
#pragma unroll
      for (int rr = 0; rr < 2; rr++) {
        const int trow = ws * 32 + mi * 16 + grp + rr * 8;
#pragma unroll
        for (int ni = 0; ni < 8; ni++) {
          const int tcol = wn + ni * 8 + (gcc << 1);
          Ts[trow * TSTRIDE + tcol]     = acc[mi][ni][rr * 2 + 0];
          Ts[trow * TSTRIDE + tcol + 1] = acc[mi][ni][rr * 2 + 1];
        }
      }
    }
    __syncthreads();
    if (tid < 128) {
      const int col = nb * 128 + tid;
      const float a = 1.f / (1.f + expf(-e_base[col]));
      const int t0 = rb * 128;
      const int t1 = (t0 + 128 < M) ? (t0 + 128) : M;
      float hv = 0.f;
      for (int t = t0; t < t1; t++) {
        hv = fmaf(a, hv, Ts[(t - t0) * TSTRIDE + tid]);
        Ts[(t - t0) * TSTRIDE + tid] = hv;
      }
      ((float*)tga)[rb * 1024 + col] = hv;
    }
    __syncthreads();
    for (int ii = tid; ii < 4096; ii += 256) {
      const int l2   = ii & 31;
      const int half = (ii >> 5) & 1;
      const int gg   = (ii >> 6) & 7;
      const int ktl  = ii >> 9;
      const int rl = gg * 16 + (l2 >> 2);
      const int cl = ktl * 16 + half * 8 + (l2 & 3);
      float4 o;
      o.x = Ts[rl * TSTRIDE + cl];
      o.y = Ts[(rl + 8) * TSTRIDE + cl];
      o.z = Ts[rl * TSTRIDE + cl + 4];
      o.w = Ts[(rl + 8) * TSTRIDE + cl + 4];
      const size_t off = ((size_t)(rb * 64 + nb * 8 + ktl)) * 2048 +
                         (((gg << 1) + half) << 7) + (l2 << 2);
      *reinterpret_cast<float4*>(C + off) = o;
    }
  }
}

// ---------------------------------------------------------------------------
// QKV GEMM with fused layernorm+RoPE+transpose epilogue.
// ---------------------------------------------------------------------------
__global__ void __launch_bounds__(256) tf32_gemm_qkv(
    const float* __restrict__ Ap, const float* __restrict__ Bp,
    const float* __restrict__ bias,
    const float* __restrict__ qn_w, const float* __restrict__ qn_b,
    const float* __restrict__ kn_w, const float* __restrict__ kn_b,
    float* __restrict__ qt, float* __restrict__ kt, float* __restrict__ vt) {
  extern __shared__ float smg[];
  float* As = smg;
  float* Bs = smg + 12288;
  const int tid = threadIdx.x;
  const int warp = tid >> 5, lane = tid & 31;
  const int ws = warp & 3;
  const int wn = (warp >> 2) << 6;
  const int grp = lane >> 2, gcc = lane & 3;
  const int rb = blockIdx.y, nb = blockIdx.x;
  const uint32_t sA = (uint32_t)__cvta_generic_to_shared(As);
  const uint32_t sB = (uint32_t)__cvta_generic_to_shared(Bs);

  GEMM_MAINLOOP(Ap + (size_t)rb * 64 * 2048, Bp + (size_t)nb * 64 * 2048)

  __syncthreads();
  float* Ts = smg;
#pragma unroll
  for (int mi = 0; mi < 2; mi++) {
#pragma unroll
    for (int rr = 0; rr < 2; rr++) {
      const int trow = ws * 32 + mi * 16 + grp + rr * 8;
#pragma unroll
      for (int ni = 0; ni < 8; ni++) {
        const int tcol = wn + ni * 8 + (gcc << 1);
        const float b0 = __ldg(bias + nb * 128 + tcol);
        const float b1 = __ldg(bias + nb * 128 + tcol + 1);
        Ts[trow * TSTRIDE + tcol]     = acc[mi][ni][rr * 2 + 0] + b0;
        Ts[trow * TSTRIDE + tcol + 1] = acc[mi][ni][rr * 2 + 1] + b1;
      }
    }
  }
  __syncthreads();

  const int tr = tid >> 1;
  const int hl = tid & 1;
  const int row = rb * 128 + tr;
  if (row >= M_ATTN) return;
  const int bc = row / T_ATTN;
  const int t  = row - bc * T_ATTN;
  const int h  = ((nb & 7) << 1) + hl;
  float x[64];
#pragma unroll
  for (int d = 0; d < 64; d += 4) {
    const float4 v4 = *reinterpret_cast<const float4*>(&Ts[tr * TSTRIDE + hl * 64 + d]);
    x[d] = v4.x; x[d+1] = v4.y; x[d+2] = v4.z; x[d+3] = v4.w;
  }
  float* outb;
  if (nb < 16) {
    const float* nw = (nb < 8) ? qn_w : kn_w;
    const float* nbi = (nb < 8) ? qn_b : kn_b;
    float sm = 0.f, ss = 0.f;
#pragma unroll
    for (int d = 0; d < 64; d++) { sm += x[d]; ss += x[d] * x[d]; }
    const float mu  = sm * (1.f / 64.f);
    const float var = ss * (1.f / 64.f) - mu * mu;
    const float rr  = rsqrtf(var + 1e-6f);
#pragma unroll
    for (int d = 0; d < 64; d++) x[d] = (x[d] - mu) * rr * nw[d] + nbi[d];
    if (t >= TXT_LEN) rope_apply(x, t);
    outb = (nb < 8) ? qt : kt;
  } else {
    outb = vt;
  }
  const size_t dst = ((size_t)(bc * NHEAD + h) * T_ATTN + t) * HDIM;
#pragma unroll
  for (int d = 0; d < 64; d += 4)
    *reinterpret_cast<float4*>(outb + dst + d) =
        make_float4(tf32_rna(x[d]), tf32_rna(x[d+1]), tf32_rna(x[d+2]), tf32_rna(x[d+3]));
}

// ---------------------------------------------------------------------------
// Coalesced A-perm writers
// ---------------------------------------------------------------------------
__global__ void gather_cur_perm4(const float* __restrict__ vid,
                                 const float* __restrict__ txt,
                                 float* __restrict__ curp) {
  const int idx = blockIdx.x * 256 + threadIdx.x;
  const APermIdx ix = aperm_decode(idx);
  auto ld = [&](int r, int c) -> float {
    if (r >= M_ATTN) return 0.f;
    const int bc = r / T_ATTN;
    const int t  = r - bc * T_ATTN;
    return (t < TXT_LEN)
        ? txt[(size_t)(bc * TXT_LEN + t) * D_MODEL + c]
        : vid[(size_t)(bc * 768 + (t - TXT_LEN)) * D_MODEL + c];
  };
  float4 o;
  o.x = tf32_rna(ld(ix.r0,     ix.c0));
  o.y = tf32_rna(ld(ix.r0 + 8, ix.c0));
  o.z = tf32_rna(ld(ix.r0,     ix.c0 + 4));
  o.w = tf32_rna(ld(ix.r0 + 8, ix.c0 + 4));
  *reinterpret_cast<float4*>(curp + ix.off) = o;
}

__global__ void build_emb_perm4(const float* __restrict__ proj,
                                float* __restrict__ emb,
                                float* __restrict__ embp) {
  const int idx = blockIdx.x * 256 + threadIdx.x;
  const APermIdx ix = aperm_decode(idx);
  auto combine = [&](int i, int c) -> float {
    if (i >= SEQ_SSM) return 0.f;
    if (i < SEQ_TXT) {
      const int ch = i / TXT_LEN;
      const int t  = i - ch * TXT_LEN;
      return proj[(size_t)(ch * SEG_PAD + t) * D_MODEL + c];
    }
    const int p = i - SEQ_TXT;
    float acc = 0.f; int cnt = 0;
#pragma unroll
    for (int ch = 0; ch < 4; ch++) {
      const int j = p - ch * 768;
      if (j >= 0 && j < CHUNK_VID) {
        acc += proj[(size_t)(ch * SEG_PAD + TXT_LEN + j) * D_MODEL + c];
        cnt++;
      }
    }
    return acc * (1.f / (float)cnt);
  };
  const float v00 = combine(ix.r0,     ix.c0);
  const float v10 = combine(ix.r0 + 8, ix.c0);
  const float v01 = combine(ix.r0,     ix.c0 + 4);
  const float v11 = combine(ix.r0 + 8, ix.c0 + 4);
  if (ix.r0 < SEQ_SSM) {
    emb[(size_t)ix.r0 * D_MODEL + ix.c0]     = v00;
    emb[(size_t)ix.r0 * D_MODEL + ix.c0 + 4] = v01;
  }
  if (ix.r0 + 8 < SEQ_SSM) {
    emb[(size_t)(ix.r0 + 8) * D_MODEL + ix.c0]     = v10;
    emb[(size_t)(ix.r0 + 8) * D_MODEL + ix.c0 + 4] = v11;
  }
  *reinterpret_cast<float4*>(embp + ix.off) =
      make_float4(tf32_rna(v00), tf32_rna(v10), tf32_rna(v01), tf32_rna(v11));
}

// ---------------------------------------------------------------------------
// Flash attention tf32, 128-row tiles, in-warp softmax, double-buffered K/V
// (buffer 1 reuses the dead Qs region; sync loads; ONE block sync per tile).
// ---------------------------------------------------------------------------
#define FS 68
#define FA_SMEM ((384 * FS) * 4)

__global__ void __launch_bounds__(256) flash_tf32_kernel(
    const float* __restrict__ Qt, const float* __restrict__ Kt,
    const float* __restrict__ Vt, float* __restrict__ Outp) {
  extern __shared__ float sm[];
  // buffers: B0 K at 128*FS, V at 192*FS ; B1 (ex-Qs) K at 0, V at 64*FS
  float* Ss = sm + 256 * FS;

  const int mat = blockIdx.y;
  const int q0  = blockIdx.x * 128;
  const int tid = threadIdx.x;
  const int warp = tid >> 5;
  const int lane = tid & 31;
  const int gr = lane >> 2;
  const int gc = lane & 3;
  const int wm = warp * 16;

  const float* Qb = Qt + (size_t)mat * T_ATTN * HDIM;
  const float* Kb = Kt + (size_t)mat * T_ATTN * HDIM;
  const float* Vb = Vt + (size_t)mat * T_ATTN * HDIM;

  // load Q tile into B-region (sm..128*FS) temporarily
  {
    float* Qs = sm;
    const int r  = tid >> 1;
    const int d0 = (tid & 1) << 5;
    const int gq = q0 + r;
#pragma unroll
    for (int i = 0; i < 32; i += 4) {
      float4 v4 = make_float4(0.f, 0.f, 0.f, 0.f);
      if (gq < T_ATTN)
        v4 = *reinterpret_cast<const float4*>(Qb + (size_t)gq * HDIM + d0 + i);
      *reinterpret_cast<float4*>(&Qs[r * FS + d0 + i]) = v4;
    }
  }
  __syncthreads();

  uint32_t qf[8][4];
  {
    const float* Qs = sm;
#pragma unroll
    for (int kb = 0; kb < 8; kb++) {
      const int base = (wm + gr) * FS + kb * 8 + gc;
      qf[kb][0] = __float_as_uint(Qs[base]);
      qf[kb][1] = __float_as_uint(Qs[base + 8 * FS]);
      qf[kb][2] = __float_as_uint(Qs[base + 4]);
      qf[kb][3] = __float_as_uint(Qs[base + 8 * FS + 4]);
    }
  }

  // prologue: load KV tile 0 into B0 (disjoint from Qs region, no sync needed)
  const int ldr = tid >> 2;
  const int ldd = (tid & 3) << 4;
  {
    float* K0 = sm + 128 * FS;
    float* V0 = sm + 192 * FS;
    const int gk = ldr;    // tile 0: rows 0..63, all < T_ATTN
#pragma unroll
    for (int i = 0; i < 16; i += 4) {
      *reinterpret_cast<float4*>(&K0[ldr * FS + ldd + i]) =
          *reinterpret_cast<const float4*>(Kb + (size_t)gk * HDIM + ldd + i);
      *reinterpret_cast<float4*>(&V0[ldr * FS + ldd + i]) =
          *reinterpret_cast<const float4*>(Vb + (size_t)gk * HDIM + ldd + i);
    }
  }
  __syncthreads();   // covers: qf extraction done (Qs region now reusable) + KV0 visible

  float acc[8][4];
#pragma unroll
  for (int ni = 0; ni < 8; ni++)
#pragma unroll
    for (int j = 0; j < 4; j++) acc[ni][j] = 0.f;

  float mrun0 = -1e30f, mrun1 = -1e30f;
  float lrun0 = 0.f, lrun1 = 0.f;

  const int NT = (T_ATTN + 63) >> 6;   // 20
  for (int it = 0; it < NT; it++) {
    const int buf = it & 1;
    const float* Ks = (buf == 0) ? (sm + 128 * FS) : sm;
    const float* Vs = (buf == 0) ? (sm + 192 * FS) : (sm + 64 * FS);
    const int k0 = it * 64;

    // S = Q @ K^T
    float sacc[8][4];
#pragma unroll
    for (int ni = 0; ni < 8; ni++)
#pragma unroll
      for (int j = 0; j < 4; j++) sacc[ni][j] = 0.f;
#pragma unroll
    for (int kb = 0; kb < 8; kb++) {
      uint32_t bf[8][2];
#pragma unroll
      for (int ni = 0; ni < 8; ni++) {
        const int kbase = (ni * 8 + gr) * FS + kb * 8 + gc;
        bf[ni][0] = __float_as_uint(Ks[kbase]);
        bf[ni][1] = __float_as_uint(Ks[kbase + 4]);
      }
#pragma unroll
      for (int ni = 0; ni < 8; ni++) {
        asm volatile(
            "mma.sync.aligned.m16n8k8.row.col.f32.tf32.tf32.f32 "
            "{%0,%1,%2,%3}, {%4,%5,%6,%7}, {%8,%9}, {%0,%1,%2,%3};"
            : "+f"(sacc[ni][0]), "+f"(sacc[ni][1]),
              "+f"(sacc[ni][2]), "+f"(sacc[ni][3])
            : "r"(qf[kb][0]), "r"(qf[kb][1]), "r"(qf[kb][2]), "r"(qf[kb][3]),
              "r"(bf[ni][0]), "r"(bf[ni][1]));
      }
    }

    // in-register softmax
    float m0 = -1e30f, m1 = -1e30f;
#pragma unroll
    for (int ni = 0; ni < 8; ni++) {
      const int gk = k0 + ni * 8 + (gc << 1);
      sacc[ni][0] = (gk     < T_ATTN) ? sacc[ni][0] * ATTN_SCALE : -1e30f;
      sacc[ni][1] = (gk + 1 < T_ATTN) ? sacc[ni][1] * ATTN_SCALE : -1e30f;
      sacc[ni][2] = (gk     < T_ATTN) ? sacc[ni][2] * ATTN_SCALE : -1e30f;
      sacc[ni][3] = (gk + 1 < T_ATTN) ? sacc[ni][3] * ATTN_SCALE : -1e30f;
      m0 = fmaxf(m0, fmaxf(sacc[ni][0], sacc[ni][1]));
      m1 = fmaxf(m1, fmaxf(sacc[ni][2], sacc[ni][3]));
    }
    m0 = fmaxf(m0, __shfl_xor_sync(0xffffffffu, m0, 1));
    m0 = fmaxf(m0, __shfl_xor_sync(0xffffffffu, m0, 2));
    m1 = fmaxf(m1, __shfl_xor_sync(0xffffffffu, m1, 1));
    m1 = fmaxf(m1, __shfl_xor_sync(0xffffffffu, m1, 2));
    const float mn0 = fmaxf(mrun0, m0);
    const float mn1 = fmaxf(mrun1, m1);
    const float sc0 = __expf(mrun0 - mn0);
    const float sc1 = __expf(mrun1 - mn1);
    mrun0 = mn0; mrun1 = mn1;

    float s0 = 0.f, s1 = 0.f;
#pragma unroll
    for (int ni = 0; ni < 8; ni++) {
      sacc[ni][0] = tf32_rna(__expf(sacc[ni][0] - mn0));
      sacc[ni][1] = tf32_rna(__expf(sacc[ni][1] - mn0));
      sacc[ni][2] = tf32_rna(__expf(sacc[ni][2] - mn1));
      sacc[ni][3] = tf32_rna(__expf(sacc[ni][3] - mn1));
      s0 += sacc[ni][0] + sacc[ni][1];
      s1 += sacc[ni][2] + sacc[ni][3];
    }
    s0 += __shfl_xor_sync(0xffffffffu, s0, 1);
    s0 += __shfl_xor_sync(0xffffffffu, s0, 2);
    s1 += __shfl_xor_sync(0xffffffffu, s1, 1);
    s1 += __shfl_xor_sync(0xffffffffu, s1, 2);
    lrun0 = lrun0 * sc0 + s0;
    lrun1 = lrun1 * sc1 + s1;

    // write P to own-warp rows of Ss
#pragma unroll
    for (int ni = 0; ni < 8; ni++) {
      const int col = ni * 8 + (gc << 1);
      *reinterpret_cast<float2*>(&Ss[(wm + gr) * FS + col]) =
          make_float2(sacc[ni][0], sacc[ni][1]);
      *reinterpret_cast<float2*>(&Ss[(wm + 8 + gr) * FS + col]) =
          make_float2(sacc[ni][2], sacc[ni][3]);
    }
    __syncwarp();

    // prefetch KV(it+1) into the other buffer (sacc is dead here)
    if (it + 1 < NT) {
      float* Kn = ((it + 1) & 1) ? sm : (sm + 128 * FS);
      float* Vn = ((it + 1) & 1) ? (sm + 64 * FS) : (sm + 192 * FS);
      const int gk = (it + 1) * 64 + ldr;
      const int gks = (gk < T_ATTN) ? gk : (T_ATTN - 1);
      const bool valid = (gk < T_ATTN);
#pragma unroll
      for (int i = 0; i < 16; i += 4) {
        float4 kv = *reinterpret_cast<const float4*>(Kb + (size_t)gks * HDIM + ldd + i);
        float4 vv = *reinterpret_cast<const float4*>(Vb + (size_t)gks * HDIM + ldd + i);
        if (!valid) { kv = make_float4(0.f,0.f,0.f,0.f); vv = make_float4(0.f,0.f,0.f,0.f); }
        *reinterpret_cast<float4*>(&Kn[ldr * FS + ldd + i]) = kv;
        *reinterpret_cast<float4*>(&Vn[ldr * FS + ldd + i]) = vv;
      }
    }

    // rescale acc, then PV
#pragma unroll
    for (int ni = 0; ni < 8; ni++) {
      acc[ni][0] *= sc0; acc[ni][1] *= sc0;
      acc[ni][2] *= sc1; acc[ni][3] *= sc1;
    }
#pragma unroll
    for (int kb = 0; kb < 8; kb++) {
      uint32_t af[4];
      const int abase = (wm + gr) * FS + kb * 8 + gc;
      af[0] = __float_as_uint(Ss[abase]);
      af[1] = __float_as_uint(Ss[abase + 8 * FS]);
      af[2] = __float_as_uint(Ss[abase + 4]);
      af[3] = __float_as_uint(Ss[abase + 8 * FS + 4]);
      uint32_t bf[8][2];
#pragma unroll
      for (int ni = 0; ni < 8; ni++) {
        const int vbase = (kb * 8 + gc) * FS + ni * 8 + gr;
        bf[ni][0] = __float_as_uint(Vs[vbase]);
        bf[ni][1] = __float_as_uint(Vs[vbase + 4 * FS]);
      }
#pragma unroll
      for (int ni = 0; ni < 8; ni++) {
        asm volatile(
            "mma.sync.aligned.m16n8k8.row.col.f32.tf32.tf32.f32 "
            "{%0,%1,%2,%3}, {%4,%5,%6,%7}, {%8,%9}, {%0,%1,%2,%3};"
            : "+f"(acc[ni][0]), "+f"(acc[ni][1]),
              "+f"(acc[ni][2]), "+f"(acc[ni][3])
            : "r"(af[0]), "r"(af[1]), "r"(af[2]), "r"(af[3]),
              "r"(bf[ni][0]), "r"(bf[ni][1]));
      }
    }
    __syncthreads();   // prefetch stores visible; readers of current buf done
  }

  // stage normalized output in Ss, coalesced perm write
  {
    const float inv0 = 1.f / lrun0;
    const float inv1 = 1.f / lrun1;
#pragma unroll
    for (int ni = 0; ni < 8; ni++) {
      const int col = ni * 8 + (gc << 1);
      Ss[(wm + gr) * FS + col]         = acc[ni][0] * inv0;
      Ss[(wm + gr) * FS + col + 1]     = acc[ni][1] * inv0;
      Ss[(wm + 8 + gr) * FS + col]     = acc[ni][2] * inv1;
      Ss[(wm + 8 + gr) * FS + col + 1] = acc[ni][3] * inv1;
    }
  }
  __syncthreads();
  {
    const int bc = mat >> 4;
    const int h  = mat & 15;
    const int rb = (bc * SEG_PAD + q0) >> 7;
    for (int ii = tid; ii < 2048; ii += 256) {
      const int l2   = ii & 31;
      const int half = (ii >> 5) & 1;
      const int ktl  = (ii >> 6) & 3;
      const int gg   = (ii >> 8) & 7;
      const int rl = gg * 16 + (l2 >> 2);
      const int cl = ktl * 16 + half * 8 + (l2 & 3);
      float4 o;
      o.x = tf32_rna(Ss[rl * FS + cl]);
      o.y = tf32_rna(Ss[(rl + 8) * FS + cl]);
      o.z = tf32_rna(Ss[rl * FS + cl + 4]);
      o.w = tf32_rna(Ss[(rl + 8) * FS + cl + 4]);
      const int kt = h * 4 + ktl;
      const size_t off = ((size_t)(rb * 64 + kt)) * 2048 +
                         (((gg << 1) + half) << 7) + (l2 << 2);
      *reinterpret_cast<float4*>(Outp + off) = o;
    }
  }
}

// ---------------------------------------------------------------------------
// SSM scan pass3 (carry prefix computed inline)
// ---------------------------------------------------------------------------
__global__ void scan_pass3_perm4(const float* __restrict__ hlocp,
                                 const float* __restrict__ gate,
                                 const float* __restrict__ carry,
                                 float* __restrict__ hp) {
  const int idx = blockIdx.x * 256 + threadIdx.x;
  const APermIdx ix = aperm_decode(idx);
  const int chunk = ix.r0 >> 7;
  const int t0 = chunk << 7;
  const float a0 = 1.f / (1.f + expf(-gate[ix.c0]));
  const float a1 = 1.f / (1.f + expf(-gate[ix.c0 + 4]));
  const float a128_0 = __powf(a0, 128.f);
  const float a128_1 = __powf(a1, 128.f);
  float cin0 = 0.f, cin1 = 0.f;
  for (int c = 0; c < chunk; c++) {
    cin0 = a128_0 * cin0 + carry[c * 1024 + ix.c0];
    cin1 = a128_1 * cin1 + carry[c * 1024 + ix.c0 + 4];
  }
  const float e = (float)(ix.r0 - t0 + 1);
  const float p0  = __powf(a0, e);
  const float p1  = __powf(a1, e);
  const float p0b = p0 * __powf(a0, 8.f);
  const float p1b = p1 * __powf(a1, 8.f);
  const float4 v = *reinterpret_cast<const float4*>(hlocp + ix.off);
  float4 o;
  o.x = (ix.r0     < SEQ_SSM) ? tf32_rna(v.x + p0  * cin0) : 0.f;
  o.y = (ix.r0 + 8 < SEQ_SSM) ? tf32_rna(v.y + p0b * cin0) : 0.f;
  o.z = (ix.r0     < SEQ_SSM) ? tf32_rna(v.z + p1  * cin1) : 0.f;
  o.w = (ix.r0 + 8 < SEQ_SSM) ? tf32_rna(v.w + p1b * cin1) : 0.f;
  *reinterpret_cast<float4*>(hp + ix.off) = o;
}

// ---------------------------------------------------------------------------
// Launch
// ---------------------------------------------------------------------------
static float* sym_addr(const void* symbol) {
  void* p = nullptr;
  cudaGetSymbolAddress(&p, symbol);
  return (float*)p;
}

extern "C" void kernel_launch(void* const* d_in, const int* in_sizes, int n_in,
                              void* d_out, int out_size) {
  (void)in_sizes; (void)n_in; (void)out_size;
  const float* vid   = (const float*)d_in[0];
  const float* txt   = (const float*)d_in[1];
  const float* Wq    = (const float*)d_in[2];
  const float* bq    = (const float*)d_in[3];
  const float* Wk    = (const float*)d_in[4];
  const float* bk    = (const float*)d_in[5];
  const float* Wv    = (const float*)d_in[6];
  const float* bv    = (const float*)d_in[7];
  const float* Wo    = (const float*)d_in[8];
  const float* bo    = (const float*)d_in[9];
  const float* qn_w  = (const float*)d_in[10];
  const float* qn_b  = (const float*)d_in[11];
  const float* kn_w  = (const float*)d_in[12];
  const float* kn_b  = (const float*)d_in[13];
  const float* Win   = (const float*)d_in[14];
  const float* Wout  = (const float*)d_in[15];
  const float* gate  = (const float*)d_in[16];
  const float* fg_t  = (const float*)d_in[17];
  const float* fg_v  = (const float*)d_in[18];
  const float* bg_t  = (const float*)d_in[19];
  const float* bg_v  = (const float*)d_in[20];
  float* out = (float*)d_out;

  float* curp  = sym_addr(g_curp);
  float* qt    = sym_addr(g_qt);
  float* kt    = sym_addr(g_kt);
  float* vt    = sym_addr(g_vt);
  float* attnp = sym_addr(g_attnp);
  float* proj  = sym_addr(g_proj);
  float* emb   = sym_addr(g_emb);
  float* embp  = sym_addr(g_embp);
  float* hlocp = sym_addr(g_hlocp);
  float* hp    = sym_addr(g_hp);
  float* emb2  = sym_addr(g_emb2);
  float* revp  = sym_addr(g_revp);
  float* carry = sym_addr(g_carry);
  float* wqkv  = sym_addr(g_wqkv);
  float* bqkv  = sym_addr(g_bqkv);
  float* wo_p  = sym_addr(g_wo);
  float* win_p  = sym_addr(g_win);
  float* wout_p = sym_addr(g_wout);
  float* tg     = sym_addr(g_tg);

  cudaFuncSetAttribute(flash_tf32_kernel, cudaFuncAttributeMaxDynamicSharedMemorySize, FA_SMEM);
  cudaFuncSetAttribute(tf32_gemm_perm, cudaFuncAttributeMaxDynamicSharedMemorySize, GEMM_SMEM);
  cudaFuncSetAttribute(tf32_gemm_qkv, cudaFuncAttributeMaxDynamicSharedMemorySize, GEMM_SMEM);

  pack_qkv_perm2<<<6144, 256>>>(Wq, Wk, Wv, wqkv);
  pack_small_kernel<<<4, 256>>>(bq, bk, bv, fg_t, fg_v, bg_t, bg_v, bqkv, tg);
  pack3_b_perm2<<<6144, 256>>>(Wo, Win, Wout, wo_p, win_p, wout_p);

  gather_cur_perm4<<<5120, 256>>>(vid, txt, curp);
  tf32_gemm_qkv<<<dim3(24, 40), 256, GEMM_SMEM>>>(
      curp, wqkv, bqkv, qn_w, qn_b, kn_w, kn_b, qt, kt, vt);
  flash_tf32_kernel<<<dim3(10, 64), 256, FA_SMEM>>>(qt, kt, vt, attnp);
  tf32_gemm_perm<<<dim3(8, 40), 256, GEMM_SMEM>>>(
      attnp, wo_p, bo, proj, M_PAD, 1024, nullptr, nullptr, nullptr, 0);
  build_emb_perm4<<<4352, 256>>>(proj, emb, embp);

  // forward SSM
  tf32_gemm_perm<<<dim3(8, 34), 256, GEMM_SMEM>>>(
      embp, win_p, nullptr, hlocp, SEQ_SSM, 1024, gate, carry, nullptr, 3);
  scan_pass3_perm4<<<4352, 256>>>(hlocp, gate, carry, hp);
  tf32_gemm_perm<<<dim3(8, 34), 256, GEMM_SMEM>>>(
      hp, wout_p, revp, emb2, SEQ_SSM, 1024, emb, tg, tg + 1024, 1);

  // backward SSM
  tf32_gemm_perm<<<dim3(8, 34), 256, GEMM_SMEM>>>(
      revp, win_p, nullptr, hlocp, SEQ_SSM, 1024, gate, carry, nullptr, 3);
  scan_pass3_perm4<<<4352, 256>>>(hlocp, gate, carry, hp);
  tf32_gemm_perm<<<dim3(8, 34), 256, GEMM_SMEM>>>(
      hp, wout_p, nullptr, out, SEQ_SSM, 1024, emb2, tg + 2048, tg + 3072, 2);
}